// round 7
// baseline (speedup 1.0000x reference)
#include <cuda_runtime.h>
#include <cuda_bf16.h>
#include <cstdint>

#define NN   50000
#define NE   600000
#define IND  512
#define HID  128
#define OUTD 64
#define EPSV 0.1f

#define SB   256
#define NB   ((NN + SB - 1) / SB)   // 196

// ---------------- device scratch (no allocations allowed) ----------------
__device__ float g_h [NN * HID];    // layer-0 output == raw (never overwritten)
__device__ float g_ha[NN * HID];
__device__ float g_hb[NN * HID];
__device__ float g_dinv[NN];
__device__ int   g_deg [NN];
__device__ int   g_rowptr[NN + 1];
__device__ int   g_cursor[NN];
__device__ int2  g_csr [NE];        // (src, coef-bits) in CSR-by-dst order
__device__ int   g_adst[NE];        // dst per CSR position
__device__ float g_anorm[NE];       // norm per CSR position
__device__ float g_albuf[2][NN];
__device__ float g_arbuf[2][NN];
__device__ int   g_bsum[NB];
__device__ int   g_boff[NB];
__device__ __nv_bfloat16 g_w1h[HID * IND];
__device__ __nv_bfloat16 g_w1l[HID * IND];

// ---------------- split helper: f32 -> (bf16 hi trunc, bf16 lo rn), packed --
__device__ __forceinline__ void split2(float fx, float fy, uint32_t& hi, uint32_t& lo) {
    uint32_t ix = __float_as_uint(fx), iy = __float_as_uint(fy);
    hi = __byte_perm(ix, iy, 0x7632);
    float hx = __uint_as_float(ix & 0xFFFF0000u);
    float hy = __uint_as_float(iy & 0xFFFF0000u);
    __nv_bfloat162 l2 = __floats2bfloat162_rn(fx - hx, fy - hy);
    lo = *(uint32_t*)&l2;
}

// ---------------- prep: W1 split + deg init (merged) ----------------
__global__ void prep_kernel(const float* __restrict__ W) {
    int i = blockIdx.x * blockDim.x + threadIdx.x;
    if (i * 2 < HID * IND) {
        float2 v = *(const float2*)(W + i * 2);
        uint32_t h, l;
        split2(v.x, v.y, h, l);
        *(uint32_t*)(g_w1h + i * 2) = h;
        *(uint32_t*)(g_w1l + i * 2) = l;
    }
    if (i < NN) g_deg[i] = 0;
}

__global__ void count_deg_kernel(const int* __restrict__ dst) {
    int e = blockIdx.x * blockDim.x + threadIdx.x;
    if (e < NE) atomicAdd(&g_deg[dst[e]], 1);
}

// scan stage 1: per-block sums (+ fused dinv)
__global__ void scan_partial_kernel() {
    __shared__ int sh[SB];
    int i = blockIdx.x * SB + threadIdx.x;
    int v = 0;
    if (i < NN) {
        v = g_deg[i];
        g_dinv[i] = (v > 0) ? rsqrtf((float)v) : 0.0f;
    }
    sh[threadIdx.x] = v;
    __syncthreads();
#pragma unroll
    for (int o = SB / 2; o; o >>= 1) {
        if (threadIdx.x < o) sh[threadIdx.x] += sh[threadIdx.x + o];
        __syncthreads();
    }
    if (threadIdx.x == 0) g_bsum[blockIdx.x] = sh[0];
}

__global__ void scan_bsums_kernel() {
    __shared__ int sh[256];
    int t = threadIdx.x;
    int v = (t < NB) ? g_bsum[t] : 0;
    sh[t] = v;
    __syncthreads();
#pragma unroll
    for (int o = 1; o < 256; o <<= 1) {
        int add = (t >= o) ? sh[t - o] : 0;
        __syncthreads();
        sh[t] += add;
        __syncthreads();
    }
    if (t < NB) g_boff[t] = sh[t] - v;
    if (t == 255) g_rowptr[NN] = sh[255];
}

__global__ void scan_expand_kernel() {
    __shared__ int sh[SB];
    int i = blockIdx.x * SB + threadIdx.x;
    int v = (i < NN) ? g_deg[i] : 0;
    sh[threadIdx.x] = v;
    __syncthreads();
#pragma unroll
    for (int o = 1; o < SB; o <<= 1) {
        int add = (threadIdx.x >= o) ? sh[threadIdx.x - o] : 0;
        __syncthreads();
        sh[threadIdx.x] += add;
        __syncthreads();
    }
    if (i < NN) {
        int excl = g_boff[blockIdx.x] + sh[threadIdx.x] - v;
        g_rowptr[i] = excl;
        g_cursor[i] = excl;
    }
}

__global__ void fill_csr_kernel(const int* __restrict__ src, const int* __restrict__ dst) {
    int e = blockIdx.x * blockDim.x + threadIdx.x;
    if (e < NE) {
        int s = src[e], d = dst[e];
        float nrm = g_dinv[s] * g_dinv[d];
        int p = atomicAdd(&g_cursor[d], 1);
        g_csr[p] = make_int2(s, 0);
        g_adst[p] = d;
        g_anorm[p] = nrm;
    }
}

// ---------------- GEMM1: h = relu(X @ W1^T + b1) via bf16-split mma.sync ----
// C = Ah*Bh + Ah*Bl + Al*Bh. Block tile 128x128, K chunks of 32, 8 warps.
// Fused: layer-0 al/ar dots via quad-shfl + smem reduce.
#define KC 32
#define KP 40   // padded k extent in bf16 (20 words) -> conflict-free, 16B rows

__device__ __forceinline__ uint32_t ldsm32(const __nv_bfloat16* base, int row, int k) {
    return *(const uint32_t*)(base + row * KP + k);
}

__device__ __forceinline__ void mma16816(float* d, const uint32_t* a, uint32_t b0, uint32_t b1) {
    asm volatile(
        "mma.sync.aligned.m16n8k16.row.col.f32.bf16.bf16.f32 "
        "{%0,%1,%2,%3}, {%4,%5,%6,%7}, {%8,%9}, {%0,%1,%2,%3};"
        : "+f"(d[0]), "+f"(d[1]), "+f"(d[2]), "+f"(d[3])
        : "r"(a[0]), "r"(a[1]), "r"(a[2]), "r"(a[3]), "r"(b0), "r"(b1));
}

__global__ __launch_bounds__(256) void gemm1_kernel(const float* __restrict__ X,
                                                    const float* __restrict__ bias,
                                                    const float* __restrict__ attl,
                                                    const float* __restrict__ attr) {
    __shared__ __nv_bfloat16 Ah[128 * KP];
    __shared__ __nv_bfloat16 Al[128 * KP];
    __shared__ __nv_bfloat16 Bh[128 * KP];
    __shared__ __nv_bfloat16 Bl[128 * KP];
    __shared__ float s_al[128][2];
    __shared__ float s_ar[128][2];

    const int tid  = threadIdx.x;
    const int m0   = blockIdx.x * 128;
    const int lane = tid & 31;
    const int wid  = tid >> 5;
    const int wm   = wid & 3;          // M direction (4 warps)
    const int wn   = wid >> 2;         // N direction (2 warps)
    const int wmB  = wm * 32;
    const int wnB  = wn * 64;
    const int r    = lane >> 2;
    const int c2   = (lane & 3) * 2;

    float acc[2][8][4];
#pragma unroll
    for (int mi = 0; mi < 2; mi++)
#pragma unroll
        for (int ni = 0; ni < 8; ni++)
#pragma unroll
            for (int j = 0; j < 4; j++) acc[mi][ni][j] = 0.0f;

    for (int k0 = 0; k0 < IND; k0 += KC) {
        float4 xa[4];
        uint4  wh[2], wl[2];
#pragma unroll
        for (int rr = 0; rr < 4; rr++) {
            int q   = tid + rr * 256;      // 0..1023
            int row = q >> 3;              // 0..127
            int kq  = (q & 7) * 4;
            int gr  = m0 + row;
            float4 v = make_float4(0.f, 0.f, 0.f, 0.f);
            if (gr < NN) v = *(const float4*)(X + (size_t)gr * IND + k0 + kq);
            xa[rr] = v;
        }
#pragma unroll
        for (int rr = 0; rr < 2; rr++) {
            int q   = tid + rr * 256;      // 0..511
            int row = q >> 2;              // 0..127 (hid)
            int kq8 = (q & 3) * 8;
            wh[rr] = *(const uint4*)(g_w1h + (size_t)row * IND + k0 + kq8);
            wl[rr] = *(const uint4*)(g_w1l + (size_t)row * IND + k0 + kq8);
        }
        __syncthreads();
#pragma unroll
        for (int rr = 0; rr < 4; rr++) {
            int q   = tid + rr * 256;
            int row = q >> 3;
            int kq  = (q & 7) * 4;
            uint32_t h0, l0, h1, l1;
            split2(xa[rr].x, xa[rr].y, h0, l0);
            split2(xa[rr].z, xa[rr].w, h1, l1);
            *(uint2*)(Ah + row * KP + kq) = make_uint2(h0, h1);
            *(uint2*)(Al + row * KP + kq) = make_uint2(l0, l1);
        }
#pragma unroll
        for (int rr = 0; rr < 2; rr++) {
            int q   = tid + rr * 256;
            int row = q >> 2;
            int kq8 = (q & 3) * 8;
            *(uint4*)(Bh + row * KP + kq8) = wh[rr];
            *(uint4*)(Bl + row * KP + kq8) = wl[rr];
        }
        __syncthreads();

#pragma unroll
        for (int s = 0; s < 2; s++) {
            const int kb = s * 16;
            uint32_t ah[2][4], alo[2][4];
#pragma unroll
            for (int mi = 0; mi < 2; mi++) {
                int row0 = wmB + mi * 16 + r;
                ah[mi][0]  = ldsm32(Ah, row0,     kb + c2);
                ah[mi][1]  = ldsm32(Ah, row0 + 8, kb + c2);
                ah[mi][2]  = ldsm32(Ah, row0,     kb + c2 + 8);
                ah[mi][3]  = ldsm32(Ah, row0 + 8, kb + c2 + 8);
                alo[mi][0] = ldsm32(Al, row0,     kb + c2);
                alo[mi][1] = ldsm32(Al, row0 + 8, kb + c2);
                alo[mi][2] = ldsm32(Al, row0,     kb + c2 + 8);
                alo[mi][3] = ldsm32(Al, row0 + 8, kb + c2 + 8);
            }
#pragma unroll
            for (int ni = 0; ni < 8; ni++) {
                int n = wnB + ni * 8 + r;
                uint32_t bh0 = ldsm32(Bh, n, kb + c2);
                uint32_t bh1 = ldsm32(Bh, n, kb + c2 + 8);
                uint32_t bl0 = ldsm32(Bl, n, kb + c2);
                uint32_t bl1 = ldsm32(Bl, n, kb + c2 + 8);
#pragma unroll
                for (int mi = 0; mi < 2; mi++) {
                    mma16816(acc[mi][ni], ah[mi],  bh0, bh1);
                    mma16816(acc[mi][ni], ah[mi],  bl0, bl1);
                    mma16816(acc[mi][ni], alo[mi], bh0, bh1);
                }
            }
        }
    }
    __syncthreads();   // smem arrays done; s_al/s_ar writes follow per-warp

    // epilogue: bias + relu, write g_h; fused layer-0 al/ar dot partials
#pragma unroll
    for (int mi = 0; mi < 2; mi++) {
        int rloc0 = wmB + mi * 16 + r;
        int gr0 = m0 + rloc0;
        int gr1 = gr0 + 8;
        float al0 = 0.f, ar0 = 0.f, al1 = 0.f, ar1 = 0.f;
#pragma unroll
        for (int ni = 0; ni < 8; ni++) {
            int col = wnB + ni * 8 + c2;
            float2 bb = *(const float2*)(bias + col);
            float2 o0, o1;
            o0.x = fmaxf(acc[mi][ni][0] + bb.x, 0.f);
            o0.y = fmaxf(acc[mi][ni][1] + bb.y, 0.f);
            o1.x = fmaxf(acc[mi][ni][2] + bb.x, 0.f);
            o1.y = fmaxf(acc[mi][ni][3] + bb.y, 0.f);
            if (gr0 < NN) *(float2*)(g_h + (size_t)gr0 * HID + col) = o0;
            if (gr1 < NN) *(float2*)(g_h + (size_t)gr1 * HID + col) = o1;
            float2 lv = *(const float2*)(attl + col);
            float2 rv = *(const float2*)(attr + col);
            al0 += o0.x * lv.x + o0.y * lv.y;
            ar0 += o0.x * rv.x + o0.y * rv.y;
            al1 += o1.x * lv.x + o1.y * lv.y;
            ar1 += o1.x * rv.x + o1.y * rv.y;
        }
        // quad reduce (lanes t,t^1,t^2 share rows, different cols)
#pragma unroll
        for (int off = 1; off <= 2; off <<= 1) {
            al0 += __shfl_xor_sync(0xffffffffu, al0, off);
            ar0 += __shfl_xor_sync(0xffffffffu, ar0, off);
            al1 += __shfl_xor_sync(0xffffffffu, al1, off);
            ar1 += __shfl_xor_sync(0xffffffffu, ar1, off);
        }
        if ((lane & 3) == 0) {
            s_al[rloc0][wn] = al0;  s_ar[rloc0][wn] = ar0;
            s_al[rloc0 + 8][wn] = al1;  s_ar[rloc0 + 8][wn] = ar1;
        }
    }
    __syncthreads();
    if (tid < 128) {
        int gr = m0 + tid;
        if (gr < NN) {
            g_albuf[0][gr] = s_al[tid][0] + s_al[tid][1];
            g_arbuf[0][gr] = s_ar[tid][0] + s_ar[tid][1];
        }
    }
}

// ---------------- per-layer: edge coefficient (CSR order) ----------------
__global__ void coef_kernel(int l) {
    const int cur = l & 1;
    int p = blockIdx.x * blockDim.x + threadIdx.x;
    if (p < NE) {
        int s = g_csr[p].x;
        int d = g_adst[p];
        float c = tanhf(g_albuf[cur][s] + g_arbuf[cur][d]) * g_anorm[p];
        g_csr[p].y = __float_as_int(c);
    }
}

// ---------------- aggregate (warp per dst node), tanh-free, unroll 4 -------
__global__ void agg_kernel(int l, const float* __restrict__ att_l,
                           const float* __restrict__ att_r) {
    const float* __restrict__ hin  = (l == 0) ? g_h : (l == 1 ? g_ha : g_hb);
    float* __restrict__       hout = (l == 1) ? g_hb : g_ha;
    const int nxt = (l & 1) ^ 1;

    int node = (blockIdx.x * blockDim.x + threadIdx.x) >> 5;
    int lane = threadIdx.x & 31;
    if (node >= NN) return;

    int b = g_rowptr[node], e = g_rowptr[node + 1];
    float4 acc = make_float4(0.f, 0.f, 0.f, 0.f);
    int p = b;
    for (; p + 4 <= e; p += 4) {
        int2 s0 = g_csr[p];
        int2 s1 = g_csr[p + 1];
        int2 s2 = g_csr[p + 2];
        int2 s3 = g_csr[p + 3];
        float4 h0 = *(const float4*)(hin + (size_t)s0.x * HID + lane * 4);
        float4 h1 = *(const float4*)(hin + (size_t)s1.x * HID + lane * 4);
        float4 h2 = *(const float4*)(hin + (size_t)s2.x * HID + lane * 4);
        float4 h3 = *(const float4*)(hin + (size_t)s3.x * HID + lane * 4);
        float c0 = __int_as_float(s0.y), c1 = __int_as_float(s1.y);
        float c2 = __int_as_float(s2.y), c3 = __int_as_float(s3.y);
        acc.x = fmaf(c0, h0.x, acc.x); acc.y = fmaf(c0, h0.y, acc.y);
        acc.z = fmaf(c0, h0.z, acc.z); acc.w = fmaf(c0, h0.w, acc.w);
        acc.x = fmaf(c1, h1.x, acc.x); acc.y = fmaf(c1, h1.y, acc.y);
        acc.z = fmaf(c1, h1.z, acc.z); acc.w = fmaf(c1, h1.w, acc.w);
        acc.x = fmaf(c2, h2.x, acc.x); acc.y = fmaf(c2, h2.y, acc.y);
        acc.z = fmaf(c2, h2.z, acc.z); acc.w = fmaf(c2, h2.w, acc.w);
        acc.x = fmaf(c3, h3.x, acc.x); acc.y = fmaf(c3, h3.y, acc.y);
        acc.z = fmaf(c3, h3.z, acc.z); acc.w = fmaf(c3, h3.w, acc.w);
    }
    for (; p < e; p++) {
        int2 se = g_csr[p];
        float c = __int_as_float(se.y);
        float4 hv = *(const float4*)(hin + (size_t)se.x * HID + lane * 4);
        acc.x = fmaf(c, hv.x, acc.x);
        acc.y = fmaf(c, hv.y, acc.y);
        acc.z = fmaf(c, hv.z, acc.z);
        acc.w = fmaf(c, hv.w, acc.w);
    }
    float4 rv = *(const float4*)(g_h + (size_t)node * HID + lane * 4);   // raw
    acc.x += EPSV * rv.x;
    acc.y += EPSV * rv.y;
    acc.z += EPSV * rv.z;
    acc.w += EPSV * rv.w;
    *(float4*)(hout + (size_t)node * HID + lane * 4) = acc;

    if (l < 2) {   // next-layer al/ar dots
        float4 lv  = *(const float4*)(att_l + (l + 1) * HID + lane * 4);
        float4 rv2 = *(const float4*)(att_r + (l + 1) * HID + lane * 4);
        float sl = acc.x * lv.x + acc.y * lv.y + acc.z * lv.z + acc.w * lv.w;
        float sr = acc.x * rv2.x + acc.y * rv2.y + acc.z * rv2.z + acc.w * rv2.w;
#pragma unroll
        for (int off = 16; off; off >>= 1) {
            sl += __shfl_xor_sync(0xffffffffu, sl, off);
            sr += __shfl_xor_sync(0xffffffffu, sr, off);
        }
        if (lane == 0) { g_albuf[nxt][node] = sl; g_arbuf[nxt][node] = sr; }
    }
}

// ---------------- GEMM2 + bias + log_softmax (warp per node) ----------------
__global__ __launch_bounds__(256) void gemm2_kernel(const float* __restrict__ W2,
                                                    const float* __restrict__ b2,
                                                    float* __restrict__ out, int write_emb) {
    __shared__ float W2t[HID * OUTD];
    for (int idx = threadIdx.x; idx < HID * OUTD; idx += 256) {
        int k = idx >> 6, j = idx & 63;
        W2t[idx] = W2[(size_t)j * HID + k];
    }
    __syncthreads();
    int lane = threadIdx.x & 31;
    int wib  = threadIdx.x >> 5;
    for (int node = blockIdx.x * 8 + wib; node < NN; node += gridDim.x * 8) {
        float4 hv = *(const float4*)(g_ha + (size_t)node * HID + lane * 4);
        float hreg[4] = {hv.x, hv.y, hv.z, hv.w};
        float acc0 = 0.f, acc1 = 0.f;
#pragma unroll
        for (int k = 0; k < HID; k++) {
            float hk = __shfl_sync(0xffffffffu, hreg[k & 3], k >> 2);
            acc0 = fmaf(hk, W2t[k * OUTD + lane], acc0);
            acc1 = fmaf(hk, W2t[k * OUTD + 32 + lane], acc1);
        }
        float v0 = acc0 + b2[lane];
        float v1 = acc1 + b2[lane + 32];
        float m = fmaxf(v0, v1);
#pragma unroll
        for (int off = 16; off; off >>= 1) m = fmaxf(m, __shfl_xor_sync(0xffffffffu, m, off));
        float s = expf(v0 - m) + expf(v1 - m);
#pragma unroll
        for (int off = 16; off; off >>= 1) s += __shfl_xor_sync(0xffffffffu, s, off);
        float lgt = m + logf(s);
        out[(size_t)node * OUTD + lane]      = v0 - lgt;
        out[(size_t)node * OUTD + lane + 32] = v1 - lgt;
        if (write_emb) {
            out[(size_t)NN * OUTD + (size_t)node * OUTD + lane]      = v0;
            out[(size_t)NN * OUTD + (size_t)node * OUTD + lane + 32] = v1;
        }
    }
}

// ---------------- launch ----------------
extern "C" void kernel_launch(void* const* d_in, const int* in_sizes, int n_in,
                              void* d_out, int out_size) {
    const float* x    = (const float*)d_in[0];
    const int*   ei   = (const int*)  d_in[1];
    const float* t1w  = (const float*)d_in[2];
    const float* t1b  = (const float*)d_in[3];
    const float* t2w  = (const float*)d_in[4];
    const float* t2b  = (const float*)d_in[5];
    const float* attl = (const float*)d_in[6];
    const float* attr = (const float*)d_in[7];
    const int* src = ei;
    const int* dst = ei + NE;
    float* out = (float*)d_out;
    int write_emb = (out_size >= 2 * NN * OUTD) ? 1 : 0;

    prep_kernel<<<(NN + 255) / 256, 256>>>(t1w);                         // 1 (W split + deg=0)
    count_deg_kernel<<<(NE + 255) / 256, 256>>>(dst);                    // 2
    scan_partial_kernel<<<NB, SB>>>();                                   // 3 (+dinv)
    gemm1_kernel<<<(NN + 127) / 128, 256>>>(x, t1b, attl, attr);         // 4 <- ncu target
    scan_bsums_kernel<<<1, 256>>>();                                     // 5
    scan_expand_kernel<<<NB, SB>>>();                                    // 6
    fill_csr_kernel<<<(NE + 255) / 256, 256>>>(src, dst);                // 7

    for (int l = 0; l < 3; l++) {
        coef_kernel<<<(NE + 255) / 256, 256>>>(l);                       // 8,10,12
        agg_kernel<<<(NN * 32 + 255) / 256, 256>>>(l, attl, attr);       // 9,11,13
    }

    gemm2_kernel<<<1184, 256>>>(t2w, t2b, out, write_emb);               // 14
}

// round 9
// speedup vs baseline: 1.7042x; 1.7042x over previous
#include <cuda_runtime.h>
#include <cuda_bf16.h>
#include <cstdint>

#define NN   50000
#define NE   600000
#define IND  512
#define HID  128
#define OUTD 64
#define EPSV 0.1f

#define SB   256
#define NB   ((NN + SB - 1) / SB)   // 196

// ---------------- device scratch (no allocations allowed) ----------------
__device__ float g_h [NN * HID];    // layer-0 output == raw (never overwritten)
__device__ float g_ha[NN * HID];
__device__ float g_hb[NN * HID];
__device__ float g_dinv[NN];
__device__ int   g_deg [NN];
__device__ int   g_rowptr[NN + 1];
__device__ int   g_cursor[NN];
__device__ int2  g_csr [NE];        // (src, norm-bits) in CSR-by-dst order
__device__ float g_albuf[2][NN];
__device__ float g_arbuf[2][NN];
__device__ int   g_bsum[NB];
__device__ int   g_boff[NB];
__device__ __nv_bfloat16 g_w1h[HID * IND];
__device__ __nv_bfloat16 g_w1l[HID * IND];

// ---------------- split helper: f32 -> (bf16 hi trunc, bf16 lo rn), packed --
__device__ __forceinline__ void split2(float fx, float fy, uint32_t& hi, uint32_t& lo) {
    uint32_t ix = __float_as_uint(fx), iy = __float_as_uint(fy);
    hi = __byte_perm(ix, iy, 0x7632);
    float hx = __uint_as_float(ix & 0xFFFF0000u);
    float hy = __uint_as_float(iy & 0xFFFF0000u);
    __nv_bfloat162 l2 = __floats2bfloat162_rn(fx - hx, fy - hy);
    lo = *(uint32_t*)&l2;
}

// ---------------- prep: W1 split + deg init (merged) ----------------
__global__ void prep_kernel(const float* __restrict__ W) {
    int i = blockIdx.x * blockDim.x + threadIdx.x;
    if (i * 2 < HID * IND) {
        float2 v = *(const float2*)(W + i * 2);
        uint32_t h, l;
        split2(v.x, v.y, h, l);
        *(uint32_t*)(g_w1h + i * 2) = h;
        *(uint32_t*)(g_w1l + i * 2) = l;
    }
    if (i < NN) g_deg[i] = 0;
}

__global__ void count_deg_kernel(const int* __restrict__ dst) {
    int e = blockIdx.x * blockDim.x + threadIdx.x;
    if (e < NE) atomicAdd(&g_deg[dst[e]], 1);
}

// scan stage 1: per-block sums (+ fused dinv)
__global__ void scan_partial_kernel() {
    __shared__ int sh[SB];
    int i = blockIdx.x * SB + threadIdx.x;
    int v = 0;
    if (i < NN) {
        v = g_deg[i];
        g_dinv[i] = (v > 0) ? rsqrtf((float)v) : 0.0f;
    }
    sh[threadIdx.x] = v;
    __syncthreads();
#pragma unroll
    for (int o = SB / 2; o; o >>= 1) {
        if (threadIdx.x < o) sh[threadIdx.x] += sh[threadIdx.x + o];
        __syncthreads();
    }
    if (threadIdx.x == 0) g_bsum[blockIdx.x] = sh[0];
}

__global__ void scan_bsums_kernel() {
    __shared__ int sh[256];
    int t = threadIdx.x;
    int v = (t < NB) ? g_bsum[t] : 0;
    sh[t] = v;
    __syncthreads();
#pragma unroll
    for (int o = 1; o < 256; o <<= 1) {
        int add = (t >= o) ? sh[t - o] : 0;
        __syncthreads();
        sh[t] += add;
        __syncthreads();
    }
    if (t < NB) g_boff[t] = sh[t] - v;
    if (t == 255) g_rowptr[NN] = sh[255];
}

__global__ void scan_expand_kernel() {
    __shared__ int sh[SB];
    int i = blockIdx.x * SB + threadIdx.x;
    int v = (i < NN) ? g_deg[i] : 0;
    sh[threadIdx.x] = v;
    __syncthreads();
#pragma unroll
    for (int o = 1; o < SB; o <<= 1) {
        int add = (threadIdx.x >= o) ? sh[threadIdx.x - o] : 0;
        __syncthreads();
        sh[threadIdx.x] += add;
        __syncthreads();
    }
    if (i < NN) {
        int excl = g_boff[blockIdx.x] + sh[threadIdx.x] - v;
        g_rowptr[i] = excl;
        g_cursor[i] = excl;
    }
}

__global__ void fill_csr_kernel(const int* __restrict__ src, const int* __restrict__ dst) {
    int e = blockIdx.x * blockDim.x + threadIdx.x;
    if (e < NE) {
        int s = src[e], d = dst[e];
        float nrm = g_dinv[s] * g_dinv[d];
        int p = atomicAdd(&g_cursor[d], 1);
        g_csr[p] = make_int2(s, __float_as_int(nrm));
    }
}

// ---------------- GEMM1: h = relu(X @ W1^T + b1) via bf16-split mma.sync ----
// C = Ah*Bh + Ah*Bl + Al*Bh. Block tile 128x128, K chunks of 32, 8 warps.
// Fused: layer-0 al/ar dots via quad-shfl + smem reduce.
#define KC 32
#define KP 40   // padded k extent in bf16 (20 words) -> conflict-free, 16B rows

__device__ __forceinline__ uint32_t ldsm32(const __nv_bfloat16* base, int row, int k) {
    return *(const uint32_t*)(base + row * KP + k);
}

__device__ __forceinline__ void mma16816(float* d, const uint32_t* a, uint32_t b0, uint32_t b1) {
    asm volatile(
        "mma.sync.aligned.m16n8k16.row.col.f32.bf16.bf16.f32 "
        "{%0,%1,%2,%3}, {%4,%5,%6,%7}, {%8,%9}, {%0,%1,%2,%3};"
        : "+f"(d[0]), "+f"(d[1]), "+f"(d[2]), "+f"(d[3])
        : "r"(a[0]), "r"(a[1]), "r"(a[2]), "r"(a[3]), "r"(b0), "r"(b1));
}

__global__ __launch_bounds__(256, 2) void gemm1_kernel(const float* __restrict__ X,
                                                       const float* __restrict__ bias,
                                                       const float* __restrict__ attl,
                                                       const float* __restrict__ attr) {
    __shared__ __nv_bfloat16 Ah[128 * KP];
    __shared__ __nv_bfloat16 Al[128 * KP];
    __shared__ __nv_bfloat16 Bh[128 * KP];
    __shared__ __nv_bfloat16 Bl[128 * KP];
    __shared__ float s_al[128][2];
    __shared__ float s_ar[128][2];

    const int tid  = threadIdx.x;
    const int m0   = blockIdx.x * 128;
    const int lane = tid & 31;
    const int wid  = tid >> 5;
    const int wm   = wid & 3;          // M direction (4 warps)
    const int wn   = wid >> 2;         // N direction (2 warps)
    const int wmB  = wm * 32;
    const int wnB  = wn * 64;
    const int r    = lane >> 2;
    const int c2   = (lane & 3) * 2;

    float acc[2][8][4];
#pragma unroll
    for (int mi = 0; mi < 2; mi++)
#pragma unroll
        for (int ni = 0; ni < 8; ni++)
#pragma unroll
            for (int j = 0; j < 4; j++) acc[mi][ni][j] = 0.0f;

    for (int k0 = 0; k0 < IND; k0 += KC) {
        float4 xa[4];
        uint4  wh[2], wl[2];
#pragma unroll
        for (int rr = 0; rr < 4; rr++) {
            int q   = tid + rr * 256;      // 0..1023
            int row = q >> 3;              // 0..127
            int kq  = (q & 7) * 4;
            int gr  = m0 + row;
            float4 v = make_float4(0.f, 0.f, 0.f, 0.f);
            if (gr < NN) v = *(const float4*)(X + (size_t)gr * IND + k0 + kq);
            xa[rr] = v;
        }
#pragma unroll
        for (int rr = 0; rr < 2; rr++) {
            int q   = tid + rr * 256;      // 0..511
            int row = q >> 2;              // 0..127 (hid)
            int kq8 = (q & 3) * 8;
            wh[rr] = *(const uint4*)(g_w1h + (size_t)row * IND + k0 + kq8);
            wl[rr] = *(const uint4*)(g_w1l + (size_t)row * IND + k0 + kq8);
        }
        __syncthreads();
#pragma unroll
        for (int rr = 0; rr < 4; rr++) {
            int q   = tid + rr * 256;
            int row = q >> 3;
            int kq  = (q & 7) * 4;
            uint32_t h0, l0, h1, l1;
            split2(xa[rr].x, xa[rr].y, h0, l0);
            split2(xa[rr].z, xa[rr].w, h1, l1);
            *(uint2*)(Ah + row * KP + kq) = make_uint2(h0, h1);
            *(uint2*)(Al + row * KP + kq) = make_uint2(l0, l1);
        }
#pragma unroll
        for (int rr = 0; rr < 2; rr++) {
            int q   = tid + rr * 256;
            int row = q >> 2;
            int kq8 = (q & 3) * 8;
            *(uint4*)(Bh + row * KP + kq8) = wh[rr];
            *(uint4*)(Bl + row * KP + kq8) = wl[rr];
        }
        __syncthreads();

#pragma unroll
        for (int s = 0; s < 2; s++) {
            const int kb = s * 16;
            uint32_t ah[2][4], alo[2][4];
#pragma unroll
            for (int mi = 0; mi < 2; mi++) {
                int row0 = wmB + mi * 16 + r;
                ah[mi][0]  = ldsm32(Ah, row0,     kb + c2);
                ah[mi][1]  = ldsm32(Ah, row0 + 8, kb + c2);
                ah[mi][2]  = ldsm32(Ah, row0,     kb + c2 + 8);
                ah[mi][3]  = ldsm32(Ah, row0 + 8, kb + c2 + 8);
                alo[mi][0] = ldsm32(Al, row0,     kb + c2);
                alo[mi][1] = ldsm32(Al, row0 + 8, kb + c2);
                alo[mi][2] = ldsm32(Al, row0,     kb + c2 + 8);
                alo[mi][3] = ldsm32(Al, row0 + 8, kb + c2 + 8);
            }
#pragma unroll
            for (int ni = 0; ni < 8; ni++) {
                int n = wnB + ni * 8 + r;
                uint32_t bh0 = ldsm32(Bh, n, kb + c2);
                uint32_t bh1 = ldsm32(Bh, n, kb + c2 + 8);
                uint32_t bl0 = ldsm32(Bl, n, kb + c2);
                uint32_t bl1 = ldsm32(Bl, n, kb + c2 + 8);
#pragma unroll
                for (int mi = 0; mi < 2; mi++) {
                    mma16816(acc[mi][ni], ah[mi],  bh0, bh1);
                    mma16816(acc[mi][ni], ah[mi],  bl0, bl1);
                    mma16816(acc[mi][ni], alo[mi], bh0, bh1);
                }
            }
        }
    }
    __syncthreads();   // smem tiles done; s_al/s_ar writes follow per-warp

    // epilogue: bias + relu, write g_h; fused layer-0 al/ar dot partials
#pragma unroll
    for (int mi = 0; mi < 2; mi++) {
        int rloc0 = wmB + mi * 16 + r;
        int gr0 = m0 + rloc0;
        int gr1 = gr0 + 8;
        float al0 = 0.f, ar0 = 0.f, al1 = 0.f, ar1 = 0.f;
#pragma unroll
        for (int ni = 0; ni < 8; ni++) {
            int col = wnB + ni * 8 + c2;
            float2 bb = *(const float2*)(bias + col);
            float2 o0, o1;
            o0.x = fmaxf(acc[mi][ni][0] + bb.x, 0.f);
            o0.y = fmaxf(acc[mi][ni][1] + bb.y, 0.f);
            o1.x = fmaxf(acc[mi][ni][2] + bb.x, 0.f);
            o1.y = fmaxf(acc[mi][ni][3] + bb.y, 0.f);
            if (gr0 < NN) *(float2*)(g_h + (size_t)gr0 * HID + col) = o0;
            if (gr1 < NN) *(float2*)(g_h + (size_t)gr1 * HID + col) = o1;
            float2 lv = *(const float2*)(attl + col);
            float2 rv = *(const float2*)(attr + col);
            al0 += o0.x * lv.x + o0.y * lv.y;
            ar0 += o0.x * rv.x + o0.y * rv.y;
            al1 += o1.x * lv.x + o1.y * lv.y;
            ar1 += o1.x * rv.x + o1.y * rv.y;
        }
#pragma unroll
        for (int off = 1; off <= 2; off <<= 1) {
            al0 += __shfl_xor_sync(0xffffffffu, al0, off);
            ar0 += __shfl_xor_sync(0xffffffffu, ar0, off);
            al1 += __shfl_xor_sync(0xffffffffu, al1, off);
            ar1 += __shfl_xor_sync(0xffffffffu, ar1, off);
        }
        if ((lane & 3) == 0) {
            s_al[rloc0][wn] = al0;  s_ar[rloc0][wn] = ar0;
            s_al[rloc0 + 8][wn] = al1;  s_ar[rloc0 + 8][wn] = ar1;
        }
    }
    __syncthreads();
    if (tid < 128) {
        int gr = m0 + tid;
        if (gr < NN) {
            g_albuf[0][gr] = s_al[tid][0] + s_al[tid][1];
            g_arbuf[0][gr] = s_ar[tid][0] + s_ar[tid][1];
        }
    }
}

// ---------------- aggregate (warp per dst node), lane-parallel coef --------
__global__ void agg_kernel(int l, const float* __restrict__ att_l,
                           const float* __restrict__ att_r) {
    const float* __restrict__ hin  = (l == 0) ? g_h : (l == 1 ? g_ha : g_hb);
    float* __restrict__       hout = (l == 1) ? g_hb : g_ha;
    const int cur = l & 1;
    const int nxt = cur ^ 1;

    int node = (blockIdx.x * blockDim.x + threadIdx.x) >> 5;
    int lane = threadIdx.x & 31;
    if (node >= NN) return;

    int b = g_rowptr[node], e = g_rowptr[node + 1];
    float ar_n = g_arbuf[cur][node];
    float4 acc = make_float4(0.f, 0.f, 0.f, 0.f);

    for (int base = b; base < e; base += 32) {
        int n = e - base; if (n > 32) n = 32;
        // lane-parallel coefficient: one edge per lane
        int   s_ln = 0;
        float c_ln = 0.f;
        if (lane < n) {
            int2 se = g_csr[base + lane];
            s_ln = se.x;
            c_ln = tanhf(g_albuf[cur][se.x] + ar_n) * __int_as_float(se.y);
        }
        int j = 0;
        for (; j + 4 <= n; j += 4) {
            int   s0 = __shfl_sync(0xffffffffu, s_ln, j);
            int   s1 = __shfl_sync(0xffffffffu, s_ln, j + 1);
            int   s2 = __shfl_sync(0xffffffffu, s_ln, j + 2);
            int   s3 = __shfl_sync(0xffffffffu, s_ln, j + 3);
            float c0 = __shfl_sync(0xffffffffu, c_ln, j);
            float c1 = __shfl_sync(0xffffffffu, c_ln, j + 1);
            float c2 = __shfl_sync(0xffffffffu, c_ln, j + 2);
            float c3 = __shfl_sync(0xffffffffu, c_ln, j + 3);
            float4 h0 = *(const float4*)(hin + (size_t)s0 * HID + lane * 4);
            float4 h1 = *(const float4*)(hin + (size_t)s1 * HID + lane * 4);
            float4 h2 = *(const float4*)(hin + (size_t)s2 * HID + lane * 4);
            float4 h3 = *(const float4*)(hin + (size_t)s3 * HID + lane * 4);
            acc.x = fmaf(c0, h0.x, acc.x); acc.y = fmaf(c0, h0.y, acc.y);
            acc.z = fmaf(c0, h0.z, acc.z); acc.w = fmaf(c0, h0.w, acc.w);
            acc.x = fmaf(c1, h1.x, acc.x); acc.y = fmaf(c1, h1.y, acc.y);
            acc.z = fmaf(c1, h1.z, acc.z); acc.w = fmaf(c1, h1.w, acc.w);
            acc.x = fmaf(c2, h2.x, acc.x); acc.y = fmaf(c2, h2.y, acc.y);
            acc.z = fmaf(c2, h2.z, acc.z); acc.w = fmaf(c2, h2.w, acc.w);
            acc.x = fmaf(c3, h3.x, acc.x); acc.y = fmaf(c3, h3.y, acc.y);
            acc.z = fmaf(c3, h3.z, acc.z); acc.w = fmaf(c3, h3.w, acc.w);
        }
        for (; j < n; j++) {
            int   sj = __shfl_sync(0xffffffffu, s_ln, j);
            float cj = __shfl_sync(0xffffffffu, c_ln, j);
            float4 hv = *(const float4*)(hin + (size_t)sj * HID + lane * 4);
            acc.x = fmaf(cj, hv.x, acc.x);
            acc.y = fmaf(cj, hv.y, acc.y);
            acc.z = fmaf(cj, hv.z, acc.z);
            acc.w = fmaf(cj, hv.w, acc.w);
        }
    }

    float4 rv = *(const float4*)(g_h + (size_t)node * HID + lane * 4);   // raw
    acc.x += EPSV * rv.x;
    acc.y += EPSV * rv.y;
    acc.z += EPSV * rv.z;
    acc.w += EPSV * rv.w;
    *(float4*)(hout + (size_t)node * HID + lane * 4) = acc;

    if (l < 2) {   // next-layer al/ar dots
        float4 lv  = *(const float4*)(att_l + (l + 1) * HID + lane * 4);
        float4 rv2 = *(const float4*)(att_r + (l + 1) * HID + lane * 4);
        float sl = acc.x * lv.x + acc.y * lv.y + acc.z * lv.z + acc.w * lv.w;
        float sr = acc.x * rv2.x + acc.y * rv2.y + acc.z * rv2.z + acc.w * rv2.w;
#pragma unroll
        for (int off = 16; off; off >>= 1) {
            sl += __shfl_xor_sync(0xffffffffu, sl, off);
            sr += __shfl_xor_sync(0xffffffffu, sr, off);
        }
        if (lane == 0) { g_albuf[nxt][node] = sl; g_arbuf[nxt][node] = sr; }
    }
}

// ---------------- GEMM2 + bias + log_softmax (warp per node) ----------------
__global__ __launch_bounds__(256) void gemm2_kernel(const float* __restrict__ W2,
                                                    const float* __restrict__ b2,
                                                    float* __restrict__ out, int write_emb) {
    __shared__ float W2t[HID * OUTD];
    for (int idx = threadIdx.x; idx < HID * OUTD; idx += 256) {
        int k = idx >> 6, j = idx & 63;
        W2t[idx] = W2[(size_t)j * HID + k];
    }
    __syncthreads();
    int lane = threadIdx.x & 31;
    int wib  = threadIdx.x >> 5;
    for (int node = blockIdx.x * 8 + wib; node < NN; node += gridDim.x * 8) {
        float4 hv = *(const float4*)(g_ha + (size_t)node * HID + lane * 4);
        float hreg[4] = {hv.x, hv.y, hv.z, hv.w};
        float acc0 = 0.f, acc1 = 0.f;
#pragma unroll
        for (int k = 0; k < HID; k++) {
            float hk = __shfl_sync(0xffffffffu, hreg[k & 3], k >> 2);
            acc0 = fmaf(hk, W2t[k * OUTD + lane], acc0);
            acc1 = fmaf(hk, W2t[k * OUTD + 32 + lane], acc1);
        }
        float v0 = acc0 + b2[lane];
        float v1 = acc1 + b2[lane + 32];
        float m = fmaxf(v0, v1);
#pragma unroll
        for (int off = 16; off; off >>= 1) m = fmaxf(m, __shfl_xor_sync(0xffffffffu, m, off));
        float s = expf(v0 - m) + expf(v1 - m);
#pragma unroll
        for (int off = 16; off; off >>= 1) s += __shfl_xor_sync(0xffffffffu, s, off);
        float lgt = m + logf(s);
        out[(size_t)node * OUTD + lane]      = v0 - lgt;
        out[(size_t)node * OUTD + lane + 32] = v1 - lgt;
        if (write_emb) {
            out[(size_t)NN * OUTD + (size_t)node * OUTD + lane]      = v0;
            out[(size_t)NN * OUTD + (size_t)node * OUTD + lane + 32] = v1;
        }
    }
}

// ---------------- launch ----------------
extern "C" void kernel_launch(void* const* d_in, const int* in_sizes, int n_in,
                              void* d_out, int out_size) {
    const float* x    = (const float*)d_in[0];
    const int*   ei   = (const int*)  d_in[1];
    const float* t1w  = (const float*)d_in[2];
    const float* t1b  = (const float*)d_in[3];
    const float* t2w  = (const float*)d_in[4];
    const float* t2b  = (const float*)d_in[5];
    const float* attl = (const float*)d_in[6];
    const float* attr = (const float*)d_in[7];
    const int* src = ei;
    const int* dst = ei + NE;
    float* out = (float*)d_out;
    int write_emb = (out_size >= 2 * NN * OUTD) ? 1 : 0;

    prep_kernel<<<(NN + 255) / 256, 256>>>(t1w);                         // 1 (W split + deg=0)
    count_deg_kernel<<<(NE + 255) / 256, 256>>>(dst);                    // 2
    scan_partial_kernel<<<NB, SB>>>();                                   // 3 (+dinv)
    gemm1_kernel<<<(NN + 127) / 128, 256>>>(x, t1b, attl, attr);         // 4 <- ncu target
    scan_bsums_kernel<<<1, 256>>>();                                     // 5
    scan_expand_kernel<<<NB, SB>>>();                                    // 6
    fill_csr_kernel<<<(NE + 255) / 256, 256>>>(src, dst);                // 7

    for (int l = 0; l < 3; l++) {
        agg_kernel<<<(NN * 32 + 255) / 256, 256>>>(l, attl, attr);       // 8,9,10
    }

    gemm2_kernel<<<1184, 256>>>(t2w, t2b, out, write_emb);               // 11
}